// round 8
// baseline (speedup 1.0000x reference)
#include <cuda_runtime.h>

// Problem constants (fixed by the reference)
#define C_CELLS 500000
#define Q 16
#define NB 10
#define THREADS_PER_CELL 4   // each thread handles 4 quadrature points (float4)

__global__ __launch_bounds__(256)
void quad_fn_kernel(
    const float*  __restrict__ vertex_dofs,     // [V,1]
    const float2* __restrict__ edge_dofs,       // [E,2] as float2
    const float*  __restrict__ face_dofs,       // [C,1]
    const float4* __restrict__ y,               // [C,NB,Q] viewed as float4: [C*NB*4]
    const int*    __restrict__ faces,           // [C,3]
    const int*    __restrict__ faces_to_edges,  // [C,3]
    const int*    __restrict__ edge_orientation,// [C,3]
    float4*       __restrict__ out)             // [C,Q] as float4: [C*4]
{
    const int gid = blockIdx.x * blockDim.x + threadIdx.x;
    const int c  = gid >> 2;          // cell
    const int qg = gid & 3;           // which float4 of the 16 q-points
    if (c >= C_CELLS) return;

    // ---- Gather local dofs (identical across the 4 lanes of this cell;
    //      warp coalesces these into single broadcast transactions) ----
    float d[NB];

    const int base3 = c * 3;
    #pragma unroll
    for (int i = 0; i < 3; ++i) {
        d[i] = __ldg(&vertex_dofs[__ldg(&faces[base3 + i])]);
    }
    #pragma unroll
    for (int i = 0; i < 3; ++i) {
        const int   e  = __ldg(&faces_to_edges[base3 + i]);
        const float2 ed = __ldg(&edge_dofs[e]);
        const int   o  = __ldg(&edge_orientation[base3 + i]);
        // orientation==1: keep (e0,e1); orientation==0: flipped (e1,e0)
        d[3 + 2 * i]     = o ? ed.x : ed.y;
        d[3 + 2 * i + 1] = o ? ed.y : ed.x;
    }
    d[9] = __ldg(&face_dofs[c]);

    // ---- Weighted sum over basis functions on a float4 of q-points ----
    // y float4 index: cell c, basis b, quad-group qg -> c*NB*4 + b*4 + qg
    const float4* yp = y + (size_t)c * (NB * 4) + qg;

    float4 acc = make_float4(0.f, 0.f, 0.f, 0.f);
    #pragma unroll
    for (int b = 0; b < NB; ++b) {
        const float4 v = __ldg(&yp[b * 4]);
        const float  w = d[b];
        acc.x = fmaf(w, v.x, acc.x);
        acc.y = fmaf(w, v.y, acc.y);
        acc.z = fmaf(w, v.z, acc.z);
        acc.w = fmaf(w, v.w, acc.w);
    }

    out[(size_t)c * 4 + qg] = acc;
}

extern "C" void kernel_launch(void* const* d_in, const int* in_sizes, int n_in,
                              void* d_out, int out_size)
{
    // metadata order: vertex_dofs, edge_dofs, face_dofs, y, faces,
    //                 faces_to_edges, edge_orientation
    const float*  vertex_dofs      = (const float*) d_in[0];
    const float2* edge_dofs        = (const float2*)d_in[1];
    const float*  face_dofs        = (const float*) d_in[2];
    const float4* y                = (const float4*)d_in[3];
    const int*    faces            = (const int*)   d_in[4];
    const int*    faces_to_edges   = (const int*)   d_in[5];
    const int*    edge_orientation = (const int*)   d_in[6];
    float4*       out              = (float4*)      d_out;

    const int total_threads = C_CELLS * THREADS_PER_CELL;  // 2,000,000
    const int block = 256;
    const int grid  = (total_threads + block - 1) / block;

    quad_fn_kernel<<<grid, block>>>(vertex_dofs, edge_dofs, face_dofs, y,
                                    faces, faces_to_edges, edge_orientation, out);
}

// round 9
// speedup vs baseline: 1.0053x; 1.0053x over previous
#include <cuda_runtime.h>

// Problem constants (fixed by the reference)
#define C_CELLS 500000
#define Q 16
#define NB 10
#define THREADS_PER_CELL 2   // each thread handles 8 quadrature points (2x float4)

__device__ __forceinline__ float4 ldcs4(const float4* p) {
    return __ldcs(p);
}

__global__ __launch_bounds__(256)
void quad_fn_kernel(
    const float*  __restrict__ vertex_dofs,     // [V,1]
    const float2* __restrict__ edge_dofs,       // [E,2] as float2
    const float*  __restrict__ face_dofs,       // [C,1]
    const float4* __restrict__ y,               // [C,NB,Q] as float4: [C*NB*4]
    const int*    __restrict__ faces,           // [C,3]
    const int*    __restrict__ faces_to_edges,  // [C,3]
    const int*    __restrict__ edge_orientation,// [C,3]
    float4*       __restrict__ out)             // [C,Q] as float4: [C*4]
{
    const int gid = blockIdx.x * blockDim.x + threadIdx.x;
    const int c = gid >> 1;          // cell
    const int h = gid & 1;           // which half (8 q-points) of the cell
    if (c >= C_CELLS) return;

    // ---- Gather local dofs (duplicated across the 2 lanes of this cell;
    //      broadcast-coalesced within the warp). Index arrays are streamed
    //      once -> .cs; dof tables are reused heavily -> keep cacheable. ----
    float d[NB];

    const int base3 = c * 3;
    int f0 = __ldcs(&faces[base3 + 0]);
    int f1 = __ldcs(&faces[base3 + 1]);
    int f2 = __ldcs(&faces[base3 + 2]);
    d[0] = __ldg(&vertex_dofs[f0]);
    d[1] = __ldg(&vertex_dofs[f1]);
    d[2] = __ldg(&vertex_dofs[f2]);

    #pragma unroll
    for (int i = 0; i < 3; ++i) {
        const int    e  = __ldcs(&faces_to_edges[base3 + i]);
        const int    o  = __ldcs(&edge_orientation[base3 + i]);
        const float2 ed = __ldg(&edge_dofs[e]);
        // orientation==1: keep (e0,e1); orientation==0: flipped (e1,e0)
        d[3 + 2 * i]     = o ? ed.x : ed.y;
        d[3 + 2 * i + 1] = o ? ed.y : ed.x;
    }
    d[9] = __ldcs(&face_dofs[c]);

    // ---- Weighted sum over basis functions on 8 q-points (2 x float4) ----
    // float4 index: c*NB*4 + b*4 + h*2 (+1)
    const float4* yp = y + (size_t)c * (NB * 4) + h * 2;

    float4 a0 = make_float4(0.f, 0.f, 0.f, 0.f);
    float4 a1 = make_float4(0.f, 0.f, 0.f, 0.f);

    #pragma unroll
    for (int b = 0; b < NB; ++b) {
        const float4 v0 = ldcs4(&yp[b * 4]);
        const float4 v1 = ldcs4(&yp[b * 4 + 1]);
        const float  w  = d[b];
        a0.x = fmaf(w, v0.x, a0.x);
        a0.y = fmaf(w, v0.y, a0.y);
        a0.z = fmaf(w, v0.z, a0.z);
        a0.w = fmaf(w, v0.w, a0.w);
        a1.x = fmaf(w, v1.x, a1.x);
        a1.y = fmaf(w, v1.y, a1.y);
        a1.z = fmaf(w, v1.z, a1.z);
        a1.w = fmaf(w, v1.w, a1.w);
    }

    float4* op = out + (size_t)c * 4 + h * 2;
    __stcs(op,     a0);
    __stcs(op + 1, a1);
}

extern "C" void kernel_launch(void* const* d_in, const int* in_sizes, int n_in,
                              void* d_out, int out_size)
{
    // metadata order: vertex_dofs, edge_dofs, face_dofs, y, faces,
    //                 faces_to_edges, edge_orientation
    const float*  vertex_dofs      = (const float*) d_in[0];
    const float2* edge_dofs        = (const float2*)d_in[1];
    const float*  face_dofs        = (const float*) d_in[2];
    const float4* y                = (const float4*)d_in[3];
    const int*    faces            = (const int*)   d_in[4];
    const int*    faces_to_edges   = (const int*)   d_in[5];
    const int*    edge_orientation = (const int*)   d_in[6];
    float4*       out              = (float4*)      d_out;

    const int total_threads = C_CELLS * THREADS_PER_CELL;  // 1,000,000
    const int block = 256;
    const int grid  = (total_threads + block - 1) / block;

    quad_fn_kernel<<<grid, block>>>(vertex_dofs, edge_dofs, face_dofs, y,
                                    faces, faces_to_edges, edge_orientation, out);
}